// round 5
// baseline (speedup 1.0000x reference)
#include <cuda_runtime.h>
#include <cuda_fp16.h>
#include <cstdint>

#define BATCH  8
#define NHEADS 8
#define SEQ    2048
#define DIN    32
#define DH     64
#define DPROJ  512

// scores are produced directly in log2-domain: (q.k) * (0.9/8) * log2(e)
#define SCALE_Q (0.1125f * 1.44269504088896f)

#define BM   128
#define BN   64
#define KSTR 72          // padded smem row stride in halfs (144 B -> conflict-free ldmatrix)

__device__ __half g_Q[(size_t)BATCH * NHEADS * SEQ * DH];
__device__ __half g_K[(size_t)BATCH * NHEADS * SEQ * DH];
__device__ __half g_V[(size_t)BATCH * NHEADS * SEQ * DH];

__device__ __forceinline__ void mma16816(float* c, const uint32_t* a, uint32_t b0, uint32_t b1) {
    asm volatile(
        "mma.sync.aligned.m16n8k16.row.col.f32.f16.f16.f32 "
        "{%0,%1,%2,%3}, {%4,%5,%6,%7}, {%8,%9}, {%0,%1,%2,%3};"
        : "+f"(c[0]), "+f"(c[1]), "+f"(c[2]), "+f"(c[3])
        : "r"(a[0]), "r"(a[1]), "r"(a[2]), "r"(a[3]), "r"(b0), "r"(b1));
}

__device__ __forceinline__ void ldsm_x4(uint32_t* r, const __half* p) {
    uint32_t addr = (uint32_t)__cvta_generic_to_shared(p);
    asm volatile("ldmatrix.sync.aligned.m8n8.x4.shared.b16 {%0,%1,%2,%3}, [%4];"
        : "=r"(r[0]), "=r"(r[1]), "=r"(r[2]), "=r"(r[3]) : "r"(addr));
}

__device__ __forceinline__ void ldsm_x4_t(uint32_t* r, const __half* p) {
    uint32_t addr = (uint32_t)__cvta_generic_to_shared(p);
    asm volatile("ldmatrix.sync.aligned.m8n8.x4.trans.shared.b16 {%0,%1,%2,%3}, [%4];"
        : "=r"(r[0]), "=r"(r[1]), "=r"(r[2]), "=r"(r[3]) : "r"(addr));
}

__device__ __forceinline__ uint32_t packh2(float lo, float hi) {
    __half2 h = __floats2half2_rn(lo, hi);
    return *reinterpret_cast<uint32_t*>(&h);
}

// ---------------------------------------------------------------------------
// Projection: out[b,h,s,d] = fp16( (X[b,s,:] . W[h*64+d,:] + bias[h*64+d]) * scale )
// One thread per (b,s) row; W tiles staged through smem per head.
// ---------------------------------------------------------------------------
__global__ __launch_bounds__(128) void proj_kernel(
    const float* __restrict__ X, const float* __restrict__ W,
    const float* __restrict__ bias, int which, float scale)
{
    __half* out = (which == 0) ? g_Q : (which == 1) ? g_K : g_V;
    const int row  = blockIdx.x * 128 + threadIdx.x;   // [0, BATCH*SEQ)
    const int b    = row / SEQ;
    const int sidx = row % SEQ;

    float x[DIN];
    {
        const float4* xr = (const float4*)(X + (size_t)row * DIN);
        #pragma unroll
        for (int i = 0; i < DIN / 4; i++) {
            float4 t = xr[i];
            x[4*i] = t.x; x[4*i+1] = t.y; x[4*i+2] = t.z; x[4*i+3] = t.w;
        }
    }

    __shared__ float4 Ws[DH][DIN / 4];
    __shared__ float  bs[DH];

    for (int h = 0; h < NHEADS; h++) {
        __syncthreads();
        for (int i = threadIdx.x; i < DH * DIN / 4; i += 128)
            Ws[i / (DIN / 4)][i % (DIN / 4)] = ((const float4*)W)[h * (DH * DIN / 4) + i];
        if (threadIdx.x < DH) bs[threadIdx.x] = bias[h * DH + threadIdx.x];
        __syncthreads();

        uint32_t vals[DH / 2];
        #pragma unroll
        for (int d2 = 0; d2 < DH / 2; d2++) {
            float acc0 = bs[2*d2], acc1 = bs[2*d2 + 1];
            #pragma unroll
            for (int c4 = 0; c4 < DIN / 4; c4++) {
                float4 w0 = Ws[2*d2][c4];
                float4 w1 = Ws[2*d2 + 1][c4];
                acc0 += x[4*c4]*w0.x + x[4*c4+1]*w0.y + x[4*c4+2]*w0.z + x[4*c4+3]*w0.w;
                acc1 += x[4*c4]*w1.x + x[4*c4+1]*w1.y + x[4*c4+2]*w1.z + x[4*c4+3]*w1.w;
            }
            vals[d2] = packh2(acc0 * scale, acc1 * scale);
        }

        __half* op = out + (((size_t)(b * NHEADS + h) * SEQ + sidx) * DH);
        #pragma unroll
        for (int i = 0; i < DH / 8; i++) {
            uint4 u = make_uint4(vals[i*4], vals[i*4+1], vals[i*4+2], vals[i*4+3]);
            ((uint4*)op)[i] = u;
        }
    }
}

// ---------------------------------------------------------------------------
// Flash attention: BM=128 q-rows per CTA, BN=64 kv per iteration, 4 warps.
// Each warp owns 32 q-rows (2 m16 tiles). Scores arrive in log2-domain
// (scale folded into Q), softmax is exp2f, P converted to fp16 for PV.
// ---------------------------------------------------------------------------
__global__ __launch_bounds__(128) void attn_kernel(float* __restrict__ out)
{
    __shared__ __align__(16) __half sQ[BM * KSTR];
    __shared__ __align__(16) __half sK[BN * KSTR];
    __shared__ __align__(16) __half sV[BN * KSTR];

    const int tid  = threadIdx.x;
    const int warp = tid >> 5;
    const int lane = tid & 31;
    const int bh   = blockIdx.y;          // b*NHEADS + h
    const int q0   = blockIdx.x * BM;

    const __half* Qg = g_Q + ((size_t)bh * SEQ + q0) * DH;
    const __half* Kg = g_K + (size_t)bh * SEQ * DH;
    const __half* Vg = g_V + (size_t)bh * SEQ * DH;

    // Q tile -> smem (one 128B row per thread)
    {
        const int4* src = (const int4*)(Qg + (size_t)tid * DH);
        int4* dst = (int4*)(sQ + tid * KSTR);
        #pragma unroll
        for (int i = 0; i < 8; i++) dst[i] = src[i];
    }
    __syncthreads();

    // Q A-fragments: qf[mt][kt] covers q-rows [warp*32+mt*16, +16), d [kt*16, +16)
    uint32_t qf[2][4][4];
    {
        const int g = lane >> 3, r = lane & 7;
        #pragma unroll
        for (int mt = 0; mt < 2; mt++)
        #pragma unroll
        for (int kt = 0; kt < 4; kt++) {
            const __half* p = &sQ[(warp*32 + mt*16 + (g & 1)*8 + r) * KSTR + kt*16 + (g >> 1)*8];
            ldsm_x4(qf[mt][kt], p);
        }
    }

    float o[2][8][4];
    float mrow[2][2], lrow[2][2];
    #pragma unroll
    for (int mt = 0; mt < 2; mt++) {
        #pragma unroll
        for (int nt = 0; nt < 8; nt++) {
            o[mt][nt][0] = 0.f; o[mt][nt][1] = 0.f; o[mt][nt][2] = 0.f; o[mt][nt][3] = 0.f;
        }
        mrow[mt][0] = mrow[mt][1] = -1e30f;
        lrow[mt][0] = lrow[mt][1] = 0.f;
    }

    for (int t = 0; t < SEQ / BN; t++) {
        // load K,V tiles (64 rows x 128B each); thread: half-row (64B)
        {
            const int r  = tid >> 1;
            const int hh = (tid & 1) * 32;
            const int4* ks = (const int4*)(Kg + (size_t)(t*BN + r) * DH + hh);
            const int4* vs = (const int4*)(Vg + (size_t)(t*BN + r) * DH + hh);
            int4* kd = (int4*)(sK + r * KSTR + hh);
            int4* vd = (int4*)(sV + r * KSTR + hh);
            #pragma unroll
            for (int i = 0; i < 4; i++) { kd[i] = ks[i]; vd[i] = vs[i]; }
        }
        __syncthreads();

        // S = Q K^T  (fp32 accum, log2-domain scores)
        float s[2][8][4];
        #pragma unroll
        for (int mt = 0; mt < 2; mt++)
        #pragma unroll
        for (int nt = 0; nt < 8; nt++) {
            s[mt][nt][0] = 0.f; s[mt][nt][1] = 0.f; s[mt][nt][2] = 0.f; s[mt][nt][3] = 0.f;
        }

        {
            const int g = lane >> 3, r = lane & 7;
            #pragma unroll
            for (int n2 = 0; n2 < 4; n2++)
            #pragma unroll
            for (int kt = 0; kt < 4; kt++) {
                uint32_t bf[4];
                const __half* p = &sK[((n2*2 + (g >> 1)) * 8 + r) * KSTR + kt*16 + (g & 1)*8];
                ldsm_x4(bf, p);
                mma16816(s[0][n2*2],     qf[0][kt], bf[0], bf[1]);
                mma16816(s[1][n2*2],     qf[1][kt], bf[0], bf[1]);
                mma16816(s[0][n2*2 + 1], qf[0][kt], bf[2], bf[3]);
                mma16816(s[1][n2*2 + 1], qf[1][kt], bf[2], bf[3]);
            }
        }

        // online softmax (pure exp2 — scale & log2e pre-folded into Q)
        #pragma unroll
        for (int mt = 0; mt < 2; mt++)
        #pragma unroll
        for (int hf = 0; hf < 2; hf++) {
            const float mold = mrow[mt][hf];
            float mx = mold;
            #pragma unroll
            for (int nt = 0; nt < 8; nt++)
                mx = fmaxf(mx, fmaxf(s[mt][nt][hf*2], s[mt][nt][hf*2 + 1]));
            mx = fmaxf(mx, __shfl_xor_sync(0xffffffffu, mx, 1));
            mx = fmaxf(mx, __shfl_xor_sync(0xffffffffu, mx, 2));
            const float alpha = exp2f(mold - mx);
            mrow[mt][hf] = mx;
            float rs = 0.f;
            #pragma unroll
            for (int nt = 0; nt < 8; nt++) {
                float p0 = exp2f(s[mt][nt][hf*2]     - mx);
                float p1 = exp2f(s[mt][nt][hf*2 + 1] - mx);
                s[mt][nt][hf*2] = p0; s[mt][nt][hf*2 + 1] = p1;
                rs += p0 + p1;
            }
            lrow[mt][hf] = lrow[mt][hf] * alpha + rs;
            #pragma unroll
            for (int nt = 0; nt < 8; nt++) {
                o[mt][nt][hf*2]     *= alpha;
                o[mt][nt][hf*2 + 1] *= alpha;
            }
        }

        // P -> fp16 A-fragments
        uint32_t pf[2][4][4];
        #pragma unroll
        for (int mt = 0; mt < 2; mt++)
        #pragma unroll
        for (int kt = 0; kt < 4; kt++) {
            pf[mt][kt][0] = packh2(s[mt][2*kt][0],     s[mt][2*kt][1]);
            pf[mt][kt][1] = packh2(s[mt][2*kt][2],     s[mt][2*kt][3]);
            pf[mt][kt][2] = packh2(s[mt][2*kt + 1][0], s[mt][2*kt + 1][1]);
            pf[mt][kt][3] = packh2(s[mt][2*kt + 1][2], s[mt][2*kt + 1][3]);
        }

        // O += P V  (V fragments via ldmatrix.trans on row-major sV)
        {
            const int g = lane >> 3, r = lane & 7;
            #pragma unroll
            for (int d2 = 0; d2 < 4; d2++)
            #pragma unroll
            for (int kt = 0; kt < 4; kt++) {
                uint32_t bf[4];
                const __half* p = &sV[(kt*16 + (g & 1)*8 + r) * KSTR + d2*16 + (g >> 1)*8];
                ldsm_x4_t(bf, p);
                mma16816(o[0][d2*2],     pf[0][kt], bf[0], bf[1]);
                mma16816(o[1][d2*2],     pf[1][kt], bf[0], bf[1]);
                mma16816(o[0][d2*2 + 1], pf[0][kt], bf[2], bf[3]);
                mma16816(o[1][d2*2 + 1], pf[1][kt], bf[2], bf[3]);
            }
        }
        __syncthreads();
    }

    // epilogue: normalize and scatter to [B, SQ, H*DH] fp32
    const int b = bh >> 3, h = bh & 7;
    #pragma unroll
    for (int mt = 0; mt < 2; mt++)
    #pragma unroll
    for (int hf = 0; hf < 2; hf++) {
        float lt = lrow[mt][hf];
        lt += __shfl_xor_sync(0xffffffffu, lt, 1);
        lt += __shfl_xor_sync(0xffffffffu, lt, 2);
        const float inv = 1.f / lt;
        const int row = q0 + warp*32 + mt*16 + hf*8 + (lane >> 2);
        float* op = out + ((size_t)b * SEQ + row) * DPROJ + h * DH + (lane & 3) * 2;
        #pragma unroll
        for (int nt = 0; nt < 8; nt++) {
            float2 v;
            v.x = o[mt][nt][hf*2]     * inv;
            v.y = o[mt][nt][hf*2 + 1] * inv;
            *(float2*)(op + nt * 8) = v;
        }
    }
}

// ---------------------------------------------------------------------------
extern "C" void kernel_launch(void* const* d_in, const int* in_sizes, int n_in,
                              void* d_out, int out_size) {
    (void)in_sizes; (void)n_in; (void)out_size;
    const float* query = (const float*)d_in[0];
    const float* key   = (const float*)d_in[1];
    const float* value = (const float*)d_in[2];
    // d_in[3] = mask (int32) — only its shape enters the reference scale, already folded.
    const float* Wq = (const float*)d_in[4];
    const float* bq = (const float*)d_in[5];
    const float* Wk = (const float*)d_in[6];
    const float* bk = (const float*)d_in[7];
    const float* Wv = (const float*)d_in[8];
    const float* bv = (const float*)d_in[9];
    float* out = (float*)d_out;

    const int nrow_blocks = (BATCH * SEQ) / 128;   // 128
    proj_kernel<<<nrow_blocks, 128>>>(query, Wq, bq, 0, SCALE_Q);
    proj_kernel<<<nrow_blocks, 128>>>(key,   Wk, bk, 1, 1.0f);
    proj_kernel<<<nrow_blocks, 128>>>(value, Wv, bv, 2, 1.0f);

    dim3 grid(SEQ / BM, BATCH * NHEADS);           // (16, 64)
    attn_kernel<<<grid, 128>>>(out);
}